// round 10
// baseline (speedup 1.0000x reference)
#include <cuda_runtime.h>
#include <cuda_fp16.h>
#include <cstdint>

// ---------------------------------------------------------------------------
// Problem constants
// ---------------------------------------------------------------------------
#define B_   16
#define C_   306
#define CP_  320      // C padded to multiple of 32
#define T_   4000
#define M_   128
#define TN_  128      // t-tile per CTA
#define KC_  32       // K chunk
#define NCHUNK 10     // CP_/KC_

#define INV0 50.0f
#define INV1 12.5f
#define INV2 3.125f

// A tile row stride (64B data + 16B pad, m-major, normal ldmatrix)
#define RS   80
// B tile row stride (k-major: 128 t * 2B = 256B data + 16B pad, trans ldmatrix)
#define RSB  272

// SMEM layout (bytes, dynamic)
#define OFF_A(s)  ((s) * 10240)            // 3 stages
#define OFF_B(s)  (30720 + (s) * 8960)     // 2 stages (32*272=8704 used)
#define SMEM_TOTAL (30720 + 2 * 8960)      // 48640

#define NTHREADS 384   // 8 consumer warps + 4 producer warps

// Scratch: normalized channel weights, fp16, layout [b][m][c] (padded)
__device__ __align__(16) __half g_w[B_ * M_ * CP_];

__device__ __forceinline__ uint32_t smem_u32(const void* p) {
    uint32_t a;
    asm("{ .reg .u64 t; cvta.to.shared.u64 t, %1; cvt.u32.u64 %0, t; }" : "=r"(a) : "l"(p));
    return a;
}

#define LDSM4(r, addr) \
    asm volatile("ldmatrix.sync.aligned.m8n8.x4.shared.b16 {%0,%1,%2,%3}, [%4];" \
        : "=r"((r)[0]), "=r"((r)[1]), "=r"((r)[2]), "=r"((r)[3]) : "r"(addr))

#define LDSM4T(r, addr) \
    asm volatile("ldmatrix.sync.aligned.m8n8.x4.trans.shared.b16 {%0,%1,%2,%3}, [%4];" \
        : "=r"((r)[0]), "=r"((r)[1]), "=r"((r)[2]), "=r"((r)[3]) : "r"(addr))

#define STS16(addr, v) \
    asm volatile("st.shared.v4.b32 [%0], {%1,%2,%3,%4};" \
        :: "r"(addr), "r"((v).x), "r"((v).y), "r"((v).z), "r"((v).w) : "memory")

#define CP16(dst, src, sz) \
    asm volatile("cp.async.cg.shared.global [%0], [%1], 16, %2;" \
        :: "r"(dst), "l"(src), "r"(sz) : "memory")

#define CP_COMMIT() asm volatile("cp.async.commit_group;" ::: "memory")

#define MMA_F16(c, a, b0, b1) \
    asm volatile("mma.sync.aligned.m16n8k16.row.col.f32.f16.f16.f32 " \
        "{%0,%1,%2,%3}, {%4,%5,%6,%7}, {%8,%9}, {%0,%1,%2,%3};" \
        : "+f"((c)[0]), "+f"((c)[1]), "+f"((c)[2]), "+f"((c)[3]) \
        : "r"((a)[0]), "r"((a)[1]), "r"((a)[2]), "r"((a)[3]), "r"(b0), "r"(b1))

// ---------------------------------------------------------------------------
// Kernel 1: gate weights -> normalized -> fp16 -> g_w [b][m][c]
// ---------------------------------------------------------------------------
__global__ void __launch_bounds__(CP_) mrm_weights_kernel(
    const float* __restrict__ pos, const float* __restrict__ tpos,
    const float* __restrict__ w1, const float* __restrict__ b1,
    const float* __restrict__ w2, const float* __restrict__ b2)
{
    __shared__ float s_w1[96], s_b1[32], s_w2[32];
    __shared__ float warp_sums[10];
    __shared__ float s_total;

    const int bm = blockIdx.x;
    const int b = bm / M_, m = bm % M_;
    const int tid = threadIdx.x;

    if (tid < 96) s_w1[tid] = w1[tid];
    else if (tid < 128) s_b1[tid - 96] = b1[tid - 96];
    else if (tid < 160) s_w2[tid - 128] = w2[tid - 128];
    __syncthreads();

    const float txp = tpos[2 * m], typ = tpos[2 * m + 1];
    const float bias2 = b2[0];

    float wv = 0.0f;
    const int c = tid;
    if (c < C_) {
        const float px = pos[((size_t)b * C_ + c) * 2 + 0];
        const float py = pos[((size_t)b * C_ + c) * 2 + 1];
        const float dx = px - txp, dy = py - typ;
        const float d2 = dx * dx + dy * dy;
        const float s0 = __expf(-d2 * INV0);
        const float s1 = __expf(-d2 * INV1);
        const float s2 = __expf(-d2 * INV2);
        float acc = bias2;
#pragma unroll
        for (int j = 0; j < 32; j++) {
            float h = s_b1[j];
            h = fmaf(s0, s_w1[j], h);
            h = fmaf(s1, s_w1[32 + j], h);
            h = fmaf(s2, s_w1[64 + j], h);
            h = fmaxf(h, 0.0f);
            acc = fmaf(h, s_w2[j], acc);
        }
        wv = acc;
    }

    float v = wv;
#pragma unroll
    for (int o = 16; o > 0; o >>= 1) v += __shfl_down_sync(0xffffffffu, v, o);
    if ((tid & 31) == 0) warp_sums[tid >> 5] = v;
    __syncthreads();
    if (tid == 0) {
        float s = 0.0f;
#pragma unroll
        for (int i = 0; i < 10; i++) s += warp_sums[i];
        s_total = s + 1e-8f;
    }
    __syncthreads();

    float wn = (c < C_) ? (wv / s_total) : 0.0f;   // padding rows get 0
    g_w[((size_t)b * M_ + m) * CP_ + c] = __float2half(wn);
}

// ---------------------------------------------------------------------------
// Kernel 2: warp-specialized fp16 HMMA GEMM, no X smem staging.
// Producers: LDG.128 fp32 X (pipelined one chunk ahead in registers) ->
// cvt fp16 -> STS.128 into K-major B tile. Consumers: ldmatrix(.trans) + MMA.
// ---------------------------------------------------------------------------
__global__ void __launch_bounds__(NTHREADS, 2) mrm_hmma_kernel(
    const float* __restrict__ x, float* __restrict__ out)
{
    extern __shared__ __align__(16) char smem[];
    const uint32_t sb = smem_u32(smem);

    const int b   = blockIdx.y;
    const int t0  = blockIdx.x * TN_;
    const int tid = threadIdx.x;
    const int lane = tid & 31;
    const bool is_producer = (tid >= 256);

    const float* xb = x + (size_t)b * C_ * T_;
    const __half* gw = g_w + (size_t)b * M_ * CP_;

    // ---------------- producer state ----------------
    const int ptid = tid - 256;        // 0..127
    const int kloc = ptid >> 4;        // 0..7  (k row within 8-row pass)
    const int tseg = ptid & 15;        // 0..15 (8-float t segment)
    const bool t_ok = (t0 + tseg * 8 + 7) < T_;
    float4 va[8];                      // X prefetch: 4 passes x 2 float4

    auto issue_A = [&](int chunk) {
        const int k0 = chunk * KC_;
        const int as = chunk % 3;
#pragma unroll
        for (int r = 0; r < 4; r++) {
            const int c = ptid + r * 128;
            const int row = c >> 2, j = c & 3;
            const __half* src = gw + (size_t)row * CP_ + k0 + j * 8;
            CP16(sb + OFF_A(as) + row * RS + j * 16, src, 16);
        }
        CP_COMMIT();
    };

    auto ldg_issue = [&](int chunk) {
        const int k0 = chunk * KC_;
#pragma unroll
        for (int q = 0; q < 4; q++) {
            const int k = k0 + q * 8 + kloc;
            if ((k < C_) && t_ok) {
                const float4* s4 = (const float4*)(xb + (size_t)k * T_ + t0 + tseg * 8);
                va[q * 2]     = s4[0];
                va[q * 2 + 1] = s4[1];
            } else {
                va[q * 2]     = make_float4(0.f, 0.f, 0.f, 0.f);
                va[q * 2 + 1] = make_float4(0.f, 0.f, 0.f, 0.f);
            }
        }
    };

    auto convert_sts = [&](int chunk) {
        const int s = chunk & 1;
        const uint32_t base = sb + OFF_B(s) + kloc * RSB + tseg * 16;
#pragma unroll
        for (int q = 0; q < 4; q++) {
            __half2 h0 = __floats2half2_rn(va[q*2].x,   va[q*2].y);
            __half2 h1 = __floats2half2_rn(va[q*2].z,   va[q*2].w);
            __half2 h2 = __floats2half2_rn(va[q*2+1].x, va[q*2+1].y);
            __half2 h3 = __floats2half2_rn(va[q*2+1].z, va[q*2+1].w);
            uint4 v = make_uint4(*(uint32_t*)&h0, *(uint32_t*)&h1,
                                 *(uint32_t*)&h2, *(uint32_t*)&h3);
            STS16(base + (uint32_t)(q * 8) * RSB, v);
        }
    };

    // ---------------- consumer setup ----------------
    const int wid = tid >> 5;
    const int warp_m = wid >> 2;        // 0..1
    const int warp_n = wid & 3;         // 0..3

    const int lr  = lane & 7;
    const int sel = lane >> 3;          // 0..3
    // A (m-major, normal ldmatrix): mat0 m0-7@k0, mat1 m8-15@k0, mat2 m0-7@k8, mat3 m8-15@k8
    const int a_row = warp_m * 64 + lr + (sel & 1) * 8;
    const int a_col = (sel >> 1) * 16;
    // B (k-major, trans ldmatrix): mat0 k0-7/n0-7, mat1 k8-15/n0-7, mat2 k0-7/n8-15, mat3 k8-15/n8-15
    const int b_krow = (sel & 1) * 8 + lr;
    const int b_ncol = warp_n * 32 + (sel >> 1) * 8;

    float acc[4][4][4];
#pragma unroll
    for (int i = 0; i < 4; i++)
#pragma unroll
        for (int j = 0; j < 4; j++)
#pragma unroll
            for (int q = 0; q < 4; q++) acc[i][j][q] = 0.0f;

    // ---------------- prologue ----------------
    if (is_producer) {
        ldg_issue(0);
        issue_A(0);
        issue_A(1);
        convert_sts(0);                 // waits on its own LDGs (once)
        ldg_issue(1);                   // chunk 1 X in flight across barrier
        asm volatile("cp.async.wait_group 1;" ::: "memory");   // A0 arrived
    }
    __syncthreads();

    // ---------------- main loop (one block barrier per iter) ----------------
    for (int i = 0; i < NCHUNK; i++) {
        if (is_producer) {
            if (i + 1 < NCHUNK) convert_sts(i + 1);   // va issued last iter: latency hidden
            if (i + 2 < NCHUNK) {
                ldg_issue(i + 2);                     // refill va for next iter
                issue_A(i + 2);
                asm volatile("cp.async.wait_group 1;" ::: "memory");
            } else {
                asm volatile("cp.async.wait_group 0;" ::: "memory");
            }
        } else {
            const uint32_t sA = sb + OFF_A(i % 3);
            const uint32_t sB = sb + OFF_B(i & 1);
#pragma unroll
            for (int ks = 0; ks < 2; ks++) {
                uint32_t af[4][4], bf[2][4];
                const uint32_t acol = ks * 32 + a_col;
#pragma unroll
                for (int g = 0; g < 2; g++)
                    LDSM4T(bf[g], sB + (uint32_t)(ks * 16 + b_krow) * RSB
                                     + (uint32_t)(b_ncol + g * 16) * 2);
#pragma unroll
                for (int mf = 0; mf < 4; mf++)
                    LDSM4(af[mf], sA + (uint32_t)(a_row + mf * 16) * RS + acol);
#pragma unroll
                for (int mf = 0; mf < 4; mf++)
#pragma unroll
                    for (int nf = 0; nf < 4; nf++) {
                        const int g = nf >> 1, s2 = (nf & 1) * 2;
                        MMA_F16(acc[mf][nf], af[mf], bf[g][s2], bf[g][s2 + 1]);
                    }
            }
        }
        __syncthreads();
    }

    // ---------------- epilogue (consumers only) ----------------
    if (!is_producer && (t0 + warp_n * 32 < T_)) {
        const int mb = warp_m * 64 + (lane >> 2);
        const int cb = t0 + warp_n * 32 + (lane & 3) * 2;
#pragma unroll
        for (int mf = 0; mf < 4; mf++) {
#pragma unroll
            for (int nf = 0; nf < 4; nf++) {
                const int m = mb + mf * 16;
                const int t = cb + nf * 8;
                float* o0 = out + ((size_t)b * M_ + m) * T_ + t;
                float* o1 = out + ((size_t)b * M_ + m + 8) * T_ + t;
                *(float2*)o0 = make_float2(acc[mf][nf][0], acc[mf][nf][1]);
                *(float2*)o1 = make_float2(acc[mf][nf][2], acc[mf][nf][3]);
            }
        }
    }
}

// ---------------------------------------------------------------------------
extern "C" void kernel_launch(void* const* d_in, const int* in_sizes, int n_in,
                              void* d_out, int out_size) {
    const float* x    = (const float*)d_in[0];
    const float* pos  = (const float*)d_in[1];
    const float* tpos = (const float*)d_in[2];
    const float* w1   = (const float*)d_in[3];
    const float* b1   = (const float*)d_in[4];
    const float* w2   = (const float*)d_in[5];
    const float* b2   = (const float*)d_in[6];
    float* out = (float*)d_out;

    cudaFuncSetAttribute(mrm_hmma_kernel,
                         cudaFuncAttributeMaxDynamicSharedMemorySize, SMEM_TOTAL);

    mrm_weights_kernel<<<B_ * M_, CP_>>>(pos, tpos, w1, b1, w2, b2);

    dim3 grid((T_ + TN_ - 1) / TN_, B_);   // 32 x 16 = 512 CTAs
    mrm_hmma_kernel<<<grid, NTHREADS, SMEM_TOTAL>>>(x, out);
}

// round 11
// speedup vs baseline: 1.5999x; 1.5999x over previous
#include <cuda_runtime.h>
#include <cuda_fp16.h>
#include <cstdint>

// ---------------------------------------------------------------------------
// Problem constants
// ---------------------------------------------------------------------------
#define B_   16
#define C_   306
#define CP_  320      // C padded to multiple of 32
#define T_   4000
#define M_   128
#define TN_  128      // t-tile per CTA
#define KC_  32       // K chunk
#define NCHUNK 10     // CP_/KC_

#define INV0 50.0f
#define INV1 12.5f
#define INV2 3.125f

// A tile row stride (64B data + 16B pad, m-major, normal ldmatrix)
#define RS   80
// B tile row stride (k-major: 128 t * 2B = 256B + 16B pad, trans ldmatrix)
#define RSB  272
// X fp32 staging row stride (512B data + 16B pad -> conflict-free LDS.128)
#define RSX  528

// SMEM layout (bytes, dynamic)
#define OFF_A(s)  ((s) * 10240)                 // 3 stages: 0..30720
#define OFF_X(s)  (30720 + (s) * 16896)         // 2 stages (32*528)
#define OFF_B(s)  (64512 + (s) * 8704)          // 2 stages (32*272)
#define SMEM_TOTAL 81920

#define NTHREADS 384   // 8 consumer warps + 4 producer warps

// Scratch: normalized channel weights, fp16, layout [b][m][c] (padded)
__device__ __align__(16) __half g_w[B_ * M_ * CP_];

__device__ __forceinline__ uint32_t smem_u32(const void* p) {
    uint32_t a;
    asm("{ .reg .u64 t; cvta.to.shared.u64 t, %1; cvt.u32.u64 %0, t; }" : "=r"(a) : "l"(p));
    return a;
}

#define LDSM4(r, addr) \
    asm volatile("ldmatrix.sync.aligned.m8n8.x4.shared.b16 {%0,%1,%2,%3}, [%4];" \
        : "=r"((r)[0]), "=r"((r)[1]), "=r"((r)[2]), "=r"((r)[3]) : "r"(addr))

#define LDSM4T(r, addr) \
    asm volatile("ldmatrix.sync.aligned.m8n8.x4.trans.shared.b16 {%0,%1,%2,%3}, [%4];" \
        : "=r"((r)[0]), "=r"((r)[1]), "=r"((r)[2]), "=r"((r)[3]) : "r"(addr))

#define LDS128(v, addr) \
    asm volatile("ld.shared.v4.b32 {%0,%1,%2,%3}, [%4];" \
        : "=r"((v).x), "=r"((v).y), "=r"((v).z), "=r"((v).w) : "r"(addr))

#define STS16(addr, v) \
    asm volatile("st.shared.v4.b32 [%0], {%1,%2,%3,%4};" \
        :: "r"(addr), "r"((v).x), "r"((v).y), "r"((v).z), "r"((v).w) : "memory")

#define CP16(dst, src, sz) \
    asm volatile("cp.async.cg.shared.global [%0], [%1], 16, %2;" \
        :: "r"(dst), "l"(src), "r"(sz) : "memory")

#define CP_COMMIT() asm volatile("cp.async.commit_group;" ::: "memory")

// Producer-only barrier (cross-thread cp.async visibility before convert).
#define PROD_BAR() asm volatile("bar.sync 1, 128;" ::: "memory")

#define MMA_F16(c, a, b0, b1) \
    asm volatile("mma.sync.aligned.m16n8k16.row.col.f32.f16.f16.f32 " \
        "{%0,%1,%2,%3}, {%4,%5,%6,%7}, {%8,%9}, {%0,%1,%2,%3};" \
        : "+f"((c)[0]), "+f"((c)[1]), "+f"((c)[2]), "+f"((c)[3]) \
        : "r"((a)[0]), "r"((a)[1]), "r"((a)[2]), "r"((a)[3]), "r"(b0), "r"(b1))

// ---------------------------------------------------------------------------
// Kernel 1: gate weights -> normalized -> fp16 -> g_w [b][m][c]
// ---------------------------------------------------------------------------
__global__ void __launch_bounds__(CP_) mrm_weights_kernel(
    const float* __restrict__ pos, const float* __restrict__ tpos,
    const float* __restrict__ w1, const float* __restrict__ b1,
    const float* __restrict__ w2, const float* __restrict__ b2)
{
    __shared__ float s_w1[96], s_b1[32], s_w2[32];
    __shared__ float warp_sums[10];
    __shared__ float s_total;

    const int bm = blockIdx.x;
    const int b = bm / M_, m = bm % M_;
    const int tid = threadIdx.x;

    if (tid < 96) s_w1[tid] = w1[tid];
    else if (tid < 128) s_b1[tid - 96] = b1[tid - 96];
    else if (tid < 160) s_w2[tid - 128] = w2[tid - 128];
    __syncthreads();

    const float txp = tpos[2 * m], typ = tpos[2 * m + 1];
    const float bias2 = b2[0];

    float wv = 0.0f;
    const int c = tid;
    if (c < C_) {
        const float px = pos[((size_t)b * C_ + c) * 2 + 0];
        const float py = pos[((size_t)b * C_ + c) * 2 + 1];
        const float dx = px - txp, dy = py - typ;
        const float d2 = dx * dx + dy * dy;
        const float s0 = __expf(-d2 * INV0);
        const float s1 = __expf(-d2 * INV1);
        const float s2 = __expf(-d2 * INV2);
        float acc = bias2;
#pragma unroll
        for (int j = 0; j < 32; j++) {
            float h = s_b1[j];
            h = fmaf(s0, s_w1[j], h);
            h = fmaf(s1, s_w1[32 + j], h);
            h = fmaf(s2, s_w1[64 + j], h);
            h = fmaxf(h, 0.0f);
            acc = fmaf(h, s_w2[j], acc);
        }
        wv = acc;
    }

    float v = wv;
#pragma unroll
    for (int o = 16; o > 0; o >>= 1) v += __shfl_down_sync(0xffffffffu, v, o);
    if ((tid & 31) == 0) warp_sums[tid >> 5] = v;
    __syncthreads();
    if (tid == 0) {
        float s = 0.0f;
#pragma unroll
        for (int i = 0; i < 10; i++) s += warp_sums[i];
        s_total = s + 1e-8f;
    }
    __syncthreads();

    float wn = (c < C_) ? (wv / s_total) : 0.0f;   // padding rows get 0
    g_w[((size_t)b * M_ + m) * CP_ + c] = __float2half(wn);
}

// ---------------------------------------------------------------------------
// Kernel 2: warp-specialized fp16 HMMA GEMM.
// Producers: cp.async X fp32 -> padded staging; row-wise vectorized convert
// (LDS.128 -> half2 -> STS.128) into K-major B tile. Consumers: ldmatrix(.trans)+MMA.
// ---------------------------------------------------------------------------
__global__ void __launch_bounds__(NTHREADS, 2) mrm_hmma_kernel(
    const float* __restrict__ x, float* __restrict__ out)
{
    extern __shared__ __align__(16) char smem[];
    const uint32_t sb = smem_u32(smem);

    const int b   = blockIdx.y;
    const int t0  = blockIdx.x * TN_;
    const int tid = threadIdx.x;
    const int lane = tid & 31;
    const bool is_producer = (tid >= 256);

    const float* xb = x + (size_t)b * C_ * T_;
    const char* xrow_base = (const char*)(xb) + (size_t)t0 * 4;
    const __half* gw = g_w + (size_t)b * M_ * CP_;

    // ---------------- producer helpers ----------------
    const int ptid = tid - 256;        // 0..127
    const int pw   = ptid >> 5;        // quarter 0..3 (uniform per producer warp)
    const int krow = ptid & 31;        // k row 0..31

    auto issue_chunk = [&](int chunk) {
        const int k0 = chunk * KC_;
        const int as = chunk % 3;
        const int xs = chunk & 1;
        // A tile: 512 x 16B chunks, 4 per thread
#pragma unroll
        for (int r = 0; r < 4; r++) {
            const int c = ptid + r * 128;
            const int row = c >> 2, j = c & 3;
            const __half* src = gw + (size_t)row * CP_ + k0 + j * 8;
            CP16(sb + OFF_A(as) + row * RS + j * 16, src, 16);
        }
        // X staging: 32 rows x 512B data (row stride RSX), 8 chunks per thread
#pragma unroll
        for (int r = 0; r < 8; r++) {
            const int c = ptid + r * 128;
            const int k = c >> 5;
            const int j = c & 31;
            const char* src = xrow_base + (size_t)(k0 + k) * (T_ * 4) + j * 16;
            const uint32_t dst = sb + OFF_X(xs) + k * RSX + j * 16;
            const uint32_t sz = ((k0 + k) < C_ && (t0 + j * 4) < T_) ? 16u : 0u;
            CP16(dst, src, sz);
        }
        CP_COMMIT();
    };

    // Row-wise convert: thread (pw, krow) handles 128B (32 floats) of X row
    // krow, producing 64B of the K-major B row. All accesses conflict-free.
    auto convert_chunk = [&](int chunk) {
        const int s = chunk & 1;
        const bool k_ok = (chunk * KC_ + krow) < C_;
        const uint32_t xsrc = sb + OFF_X(s) + krow * RSX + pw * 128;
        uint4 xv[8];
#pragma unroll
        for (int i = 0; i < 8; i++) LDS128(xv[i], xsrc + i * 16);
        const uint32_t bdst = sb + OFF_B(s) + krow * RSB + pw * 64;
#pragma unroll
        for (int q = 0; q < 4; q++) {
            float4 f0 = *(float4*)&xv[q * 2];
            float4 f1 = *(float4*)&xv[q * 2 + 1];
            if (!k_ok) { f0 = make_float4(0.f,0.f,0.f,0.f); f1 = f0; }
            __half2 h0 = __floats2half2_rn(f0.x, f0.y);
            __half2 h1 = __floats2half2_rn(f0.z, f0.w);
            __half2 h2 = __floats2half2_rn(f1.x, f1.y);
            __half2 h3 = __floats2half2_rn(f1.z, f1.w);
            uint4 v = make_uint4(*(uint32_t*)&h0, *(uint32_t*)&h1,
                                 *(uint32_t*)&h2, *(uint32_t*)&h3);
            STS16(bdst + q * 16, v);
        }
    };

    // ---------------- consumer setup ----------------
    const int wid = tid >> 5;
    const int warp_m = wid >> 2;        // 0..1
    const int warp_n = wid & 3;         // 0..3

    const int lr  = lane & 7;
    const int sel = lane >> 3;          // 0..3
    // A (m-major, normal ldmatrix)
    const int a_row = warp_m * 64 + lr + (sel & 1) * 8;
    const int a_col = (sel >> 1) * 16;
    // B (k-major, trans ldmatrix) — mapping verified in R10 (identical rel_err)
    const int b_krow = (sel & 1) * 8 + lr;
    const int b_ncol = warp_n * 32 + (sel >> 1) * 8;

    float acc[4][4][4];
#pragma unroll
    for (int i = 0; i < 4; i++)
#pragma unroll
        for (int j = 0; j < 4; j++)
#pragma unroll
            for (int q = 0; q < 4; q++) acc[i][j][q] = 0.0f;

    // ---------------- prologue ----------------
    if (is_producer) {
        issue_chunk(0);
        issue_chunk(1);
        asm volatile("cp.async.wait_group 1;" ::: "memory");
        PROD_BAR();                 // all producers' chunk-0 groups retired
        convert_chunk(0);
    }
    __syncthreads();

    // ---------------- main loop (one block barrier per iter) ----------------
    for (int i = 0; i < NCHUNK; i++) {
        if (is_producer) {
            if (i + 2 < NCHUNK) issue_chunk(i + 2);
            if (i + 1 < NCHUNK) {
                if (i + 2 < NCHUNK) asm volatile("cp.async.wait_group 1;" ::: "memory");
                else                asm volatile("cp.async.wait_group 0;" ::: "memory");
                PROD_BAR();         // cross-thread cp.async visibility
                convert_chunk(i + 1);
            }
        } else {
            const uint32_t sA = sb + OFF_A(i % 3);
            const uint32_t sB = sb + OFF_B(i & 1);
#pragma unroll
            for (int ks = 0; ks < 2; ks++) {
                uint32_t af[4][4], bf[2][4];
                const uint32_t acol = ks * 32 + a_col;
#pragma unroll
                for (int g = 0; g < 2; g++)
                    LDSM4T(bf[g], sB + (uint32_t)(ks * 16 + b_krow) * RSB
                                     + (uint32_t)(b_ncol + g * 16) * 2);
#pragma unroll
                for (int mf = 0; mf < 4; mf++)
                    LDSM4(af[mf], sA + (uint32_t)(a_row + mf * 16) * RS + acol);
#pragma unroll
                for (int mf = 0; mf < 4; mf++)
#pragma unroll
                    for (int nf = 0; nf < 4; nf++) {
                        const int g = nf >> 1, s2 = (nf & 1) * 2;
                        MMA_F16(acc[mf][nf], af[mf], bf[g][s2], bf[g][s2 + 1]);
                    }
            }
        }
        __syncthreads();
    }

    // ---------------- epilogue (consumers only) ----------------
    if (!is_producer && (t0 + warp_n * 32 < T_)) {
        const int mb = warp_m * 64 + (lane >> 2);
        const int cb = t0 + warp_n * 32 + (lane & 3) * 2;
#pragma unroll
        for (int mf = 0; mf < 4; mf++) {
#pragma unroll
            for (int nf = 0; nf < 4; nf++) {
                const int m = mb + mf * 16;
                const int t = cb + nf * 8;
                float* o0 = out + ((size_t)b * M_ + m) * T_ + t;
                float* o1 = out + ((size_t)b * M_ + m + 8) * T_ + t;
                *(float2*)o0 = make_float2(acc[mf][nf][0], acc[mf][nf][1]);
                *(float2*)o1 = make_float2(acc[mf][nf][2], acc[mf][nf][3]);
            }
        }
    }
}

// ---------------------------------------------------------------------------
extern "C" void kernel_launch(void* const* d_in, const int* in_sizes, int n_in,
                              void* d_out, int out_size) {
    const float* x    = (const float*)d_in[0];
    const float* pos  = (const float*)d_in[1];
    const float* tpos = (const float*)d_in[2];
    const float* w1   = (const float*)d_in[3];
    const float* b1   = (const float*)d_in[4];
    const float* w2   = (const float*)d_in[5];
    const float* b2   = (const float*)d_in[6];
    float* out = (float*)d_out;

    cudaFuncSetAttribute(mrm_hmma_kernel,
                         cudaFuncAttributeMaxDynamicSharedMemorySize, SMEM_TOTAL);

    mrm_weights_kernel<<<B_ * M_, CP_>>>(pos, tpos, w1, b1, w2, b2);

    dim3 grid((T_ + TN_ - 1) / TN_, B_);   // 32 x 16 = 512 CTAs
    mrm_hmma_kernel<<<grid, NTHREADS, SMEM_TOTAL>>>(x, out);
}